// round 5
// baseline (speedup 1.0000x reference)
#include <cuda_runtime.h>

// Sum-reduce 20M fp32 values. Indices input unused (full sparse sum == values.sum()).
// HBM-bound: 80 MB read. Strategy: float4 grid-stride loads, intra-warp shuffle
// reduction, per-block atomicAdd into d_out[0].

__global__ void zero_out_kernel(float* out) {
    out[0] = 0.0f;
}

__global__ void __launch_bounds__(256) sum_kernel(const float* __restrict__ vals,
                                                  long long n, float* __restrict__ out) {
    long long n4 = n >> 2;  // number of float4s
    const float4* v4 = reinterpret_cast<const float4*>(vals);

    float acc = 0.0f;
    long long idx = blockIdx.x * (long long)blockDim.x + threadIdx.x;
    long long stride = (long long)gridDim.x * blockDim.x;

    for (long long i = idx; i < n4; i += stride) {
        float4 v = v4[i];
        acc += (v.x + v.y) + (v.z + v.w);
    }
    // tail (n not divisible by 4)
    for (long long i = (n4 << 2) + idx; i < n; i += stride) {
        acc += vals[i];
    }

    // warp reduce
    #pragma unroll
    for (int off = 16; off > 0; off >>= 1)
        acc += __shfl_down_sync(0xFFFFFFFFu, acc, off);

    __shared__ float warp_sums[8];  // 256 threads = 8 warps
    int lane = threadIdx.x & 31;
    int wid  = threadIdx.x >> 5;
    if (lane == 0) warp_sums[wid] = acc;
    __syncthreads();

    if (wid == 0) {
        float s = (lane < 8) ? warp_sums[lane] : 0.0f;
        #pragma unroll
        for (int off = 4; off > 0; off >>= 1)
            s += __shfl_down_sync(0xFFFFFFFFu, s, off);
        if (lane == 0) atomicAdd(out, s);
    }
}

extern "C" void kernel_launch(void* const* d_in, const int* in_sizes, int n_in,
                              void* d_out, int out_size) {
    const float* vals = (const float*)d_in[0];
    long long n = (long long)in_sizes[0];
    float* out = (float*)d_out;

    zero_out_kernel<<<1, 1>>>(out);
    // 148 SMs; 8 blocks/SM for good MLP depth across L1tex queues
    int grid = 148 * 8;
    sum_kernel<<<grid, 256>>>(vals, n, out);
}